// round 3
// baseline (speedup 1.0000x reference)
#include <cuda_runtime.h>
#include <cuda_bf16.h>
#include <cstdint>

#define N_VARS_MAX    1000000
#define N_CONSTRS_MAX 500000

__device__ float        g_probs[N_VARS_MAX];
__device__ float        g_ax[N_CONSTRS_MAX];
__device__ double       g_sum;
__device__ unsigned int g_done;

// ---------------------------------------------------------------------------
// Kernel 1: probs = sigmoid(pred) (float4); zero ax (float4); zero scalars
// ---------------------------------------------------------------------------
__global__ void init_kernel(const float* __restrict__ pred, int n_vars, int n_constrs)
{
    int i = blockIdx.x * blockDim.x + threadIdx.x;

    int nv4 = n_vars >> 2;
    if (i < nv4) {
        float4 x = reinterpret_cast<const float4*>(pred)[i];
        float4 p;
        p.x = 1.0f / (1.0f + __expf(-x.x));
        p.y = 1.0f / (1.0f + __expf(-x.y));
        p.z = 1.0f / (1.0f + __expf(-x.z));
        p.w = 1.0f / (1.0f + __expf(-x.w));
        reinterpret_cast<float4*>(g_probs)[i] = p;
    }
    int nc4 = n_constrs >> 2;
    if (i < nc4) {
        reinterpret_cast<float4*>(g_ax)[i] = make_float4(0.f, 0.f, 0.f, 0.f);
    }
    if (i == 0) {
        for (int j = nv4 << 2; j < n_vars; j++)
            g_probs[j] = 1.0f / (1.0f + __expf(-pred[j]));
        for (int j = nc4 << 2; j < n_constrs; j++)
            g_ax[j] = 0.0f;
        g_sum  = 0.0;
        g_done = 0u;
    }
}

// ---------------------------------------------------------------------------
// Kernel 2: scatter — red.global ax[cidx] += coeff * probs[vidx]
// 8 nnz per thread. COO streams loaded with .cs (evict-first) so L2 keeps
// the hot probs (4MB) + ax (2MB) tables resident. 8 gathers front-batched
// for MLP, then 8 no-return REDs.
// ---------------------------------------------------------------------------
__device__ __forceinline__ void red_add_f32(float* addr, float val)
{
    asm volatile("red.global.add.f32 [%0], %1;" :: "l"(addr), "f"(val) : "memory");
}

__global__ void scatter_kernel(const int*   __restrict__ constr_idx,
                               const int*   __restrict__ var_idx,
                               const float* __restrict__ coeff,
                               int nnz)
{
    int ngrp = nnz >> 3;  // groups of 8
    int i = blockIdx.x * blockDim.x + threadIdx.x;
    if (i < ngrp) {
        const int4*   ci4 = reinterpret_cast<const int4*>(constr_idx) + 2 * i;
        const int4*   vi4 = reinterpret_cast<const int4*>(var_idx)    + 2 * i;
        const float4* co4 = reinterpret_cast<const float4*>(coeff)    + 2 * i;

        // streaming (evict-first) loads of the COO arrays
        int4   ciA = __ldcs(ci4 + 0);
        int4   ciB = __ldcs(ci4 + 1);
        int4   viA = __ldcs(vi4 + 0);
        int4   viB = __ldcs(vi4 + 1);
        float4 coA = __ldcs(co4 + 0);
        float4 coB = __ldcs(co4 + 1);

        // 8 independent gathers (MLP=8) before any RED
        float p0 = __ldg(&g_probs[viA.x]);
        float p1 = __ldg(&g_probs[viA.y]);
        float p2 = __ldg(&g_probs[viA.z]);
        float p3 = __ldg(&g_probs[viA.w]);
        float p4 = __ldg(&g_probs[viB.x]);
        float p5 = __ldg(&g_probs[viB.y]);
        float p6 = __ldg(&g_probs[viB.z]);
        float p7 = __ldg(&g_probs[viB.w]);

        red_add_f32(&g_ax[ciA.x], coA.x * p0);
        red_add_f32(&g_ax[ciA.y], coA.y * p1);
        red_add_f32(&g_ax[ciA.z], coA.z * p2);
        red_add_f32(&g_ax[ciA.w], coA.w * p3);
        red_add_f32(&g_ax[ciB.x], coB.x * p4);
        red_add_f32(&g_ax[ciB.y], coB.y * p5);
        red_add_f32(&g_ax[ciB.z], coB.z * p6);
        red_add_f32(&g_ax[ciB.w], coB.w * p7);
    }
    // tail (nnz % 8)
    if (i == 0) {
        for (int j = ngrp << 3; j < nnz; j++)
            red_add_f32(&g_ax[constr_idx[j]], coeff[j] * __ldg(&g_probs[var_idx[j]]));
    }
}

// ---------------------------------------------------------------------------
// Kernel 3: violations + two-level reduce; last block writes the mean.
// ---------------------------------------------------------------------------
__global__ void reduce_kernel(const float* __restrict__ rhs,
                              const int*   __restrict__ sense,
                              int n_constrs,
                              float* __restrict__ out,
                              int n_blocks)
{
    float local = 0.0f;
    int stride = gridDim.x * blockDim.x;
    int nc4 = n_constrs >> 2;
    for (int i = blockIdx.x * blockDim.x + threadIdx.x; i < nc4; i += stride) {
        float4 ax = reinterpret_cast<const float4*>(g_ax)[i];
        float4 r  = reinterpret_cast<const float4*>(rhs)[i];
        int4   s  = reinterpret_cast<const int4*>(sense)[i];

        float d0 = ax.x - r.x, d1 = ax.y - r.y, d2 = ax.z - r.z, d3 = ax.w - r.w;
        float v0 = (s.x == 1) ? fmaxf(d0, 0.f) : (s.x == 2) ? fmaxf(-d0, 0.f) : (s.x == 3) ? fabsf(d0) : 0.f;
        float v1 = (s.y == 1) ? fmaxf(d1, 0.f) : (s.y == 2) ? fmaxf(-d1, 0.f) : (s.y == 3) ? fabsf(d1) : 0.f;
        float v2 = (s.z == 1) ? fmaxf(d2, 0.f) : (s.z == 2) ? fmaxf(-d2, 0.f) : (s.z == 3) ? fabsf(d2) : 0.f;
        float v3 = (s.w == 1) ? fmaxf(d3, 0.f) : (s.w == 2) ? fmaxf(-d3, 0.f) : (s.w == 3) ? fabsf(d3) : 0.f;
        local += (v0 + v1) + (v2 + v3);
    }
    if (blockIdx.x == 0 && threadIdx.x == 0) {
        for (int j = nc4 << 2; j < n_constrs; j++) {
            float d = g_ax[j] - rhs[j];
            int   s = sense[j];
            local += (s == 1) ? fmaxf(d, 0.f) : (s == 2) ? fmaxf(-d, 0.f) : (s == 3) ? fabsf(d) : 0.f;
        }
    }

    #pragma unroll
    for (int off = 16; off > 0; off >>= 1)
        local += __shfl_xor_sync(0xFFFFFFFFu, local, off);

    __shared__ float warp_sums[32];
    int lane = threadIdx.x & 31;
    int wid  = threadIdx.x >> 5;
    if (lane == 0) warp_sums[wid] = local;
    __syncthreads();
    int nwarps = blockDim.x >> 5;

    __shared__ bool is_last;
    if (wid == 0) {
        float b = (lane < nwarps) ? warp_sums[lane] : 0.0f;
        #pragma unroll
        for (int off = 16; off > 0; off >>= 1)
            b += __shfl_xor_sync(0xFFFFFFFFu, b, off);
        if (lane == 0) {
            atomicAdd(&g_sum, (double)b);
            __threadfence();
            unsigned int ticket = atomicInc(&g_done, (unsigned int)(n_blocks - 1));
            is_last = (ticket == (unsigned int)(n_blocks - 1));
        }
    }
    __syncthreads();
    if (is_last && threadIdx.x == 0) {
        out[0] = (float)(g_sum / (double)n_constrs);
    }
}

// ---------------------------------------------------------------------------
// Launch
// ---------------------------------------------------------------------------
extern "C" void kernel_launch(void* const* d_in, const int* in_sizes, int n_in,
                              void* d_out, int out_size)
{
    const float* pred       = (const float*)d_in[0];
    const int*   constr_idx = (const int*)  d_in[1];
    const int*   var_idx    = (const int*)  d_in[2];
    const float* coeff      = (const float*)d_in[3];
    const float* rhs        = (const float*)d_in[4];
    const int*   sense      = (const int*)  d_in[5];

    int n_vars    = in_sizes[0];
    int nnz       = in_sizes[1];
    int n_constrs = in_sizes[4];

    // 1) init
    {
        int nv4 = n_vars >> 2, nc4 = n_constrs >> 2;
        int n = (nv4 > nc4) ? nv4 : nc4;
        int threads = 256;
        int blocks  = (n + threads - 1) / threads;
        init_kernel<<<blocks, threads>>>(pred, n_vars, n_constrs);
    }

    // 2) scatter — 8 nnz per thread, exact grid
    {
        int threads = 256;
        int ngrp    = nnz >> 3;
        int blocks  = (ngrp + threads - 1) / threads;
        if (blocks < 1) blocks = 1;
        scatter_kernel<<<blocks, threads>>>(constr_idx, var_idx, coeff, nnz);
    }

    // 3) reduce + finalize fused
    {
        int threads = 256;
        int work    = n_constrs >> 2;
        int blocks  = (work + threads * 4 - 1) / (threads * 4);
        if (blocks < 1) blocks = 1;
        reduce_kernel<<<blocks, threads>>>(rhs, sense, n_constrs, (float*)d_out, blocks);
    }
}

// round 4
// speedup vs baseline: 1.0340x; 1.0340x over previous
#include <cuda_runtime.h>
#include <cuda_bf16.h>
#include <cstdint>

#define N_VARS_MAX    1000000
#define N_CONSTRS_MAX 500000

// Zero-initialized at module load; reduce_kernel restores zeros after each use,
// so every kernel_launch call sees ax == 0 (graph-replay safe, deterministic).
__device__ float        g_ax[N_CONSTRS_MAX];
__device__ double       g_sum;          // reset by last reduce block each call
__device__ unsigned int g_done;         // wraps back to 0 via atomicInc

// ---------------------------------------------------------------------------
// Kernel 1: fused sigmoid + scatter.
//   ax[cidx] += coeff * sigmoid(pred[vidx])
// 4 nnz per thread (R2's best config: plain loads, MLP=4, exact grid).
// Redundant sigmoids are free: MUFU/FMA pipes idle in this LSU-bound kernel.
// ---------------------------------------------------------------------------
__device__ __forceinline__ void red_add_f32(float* addr, float val)
{
    asm volatile("red.global.add.f32 [%0], %1;" :: "l"(addr), "f"(val) : "memory");
}

__device__ __forceinline__ float sigmoidf_fast(float x)
{
    return 1.0f / (1.0f + __expf(-x));
}

__global__ void scatter_kernel(const float* __restrict__ pred,
                               const int*   __restrict__ constr_idx,
                               const int*   __restrict__ var_idx,
                               const float* __restrict__ coeff,
                               int nnz)
{
    int nvec = nnz >> 2;
    int i = blockIdx.x * blockDim.x + threadIdx.x;
    if (i < nvec) {
        int4   ci = reinterpret_cast<const int4*>(constr_idx)[i];
        int4   vi = reinterpret_cast<const int4*>(var_idx)[i];
        float4 co = reinterpret_cast<const float4*>(coeff)[i];

        // 4 independent gathers first (MLP=4)
        float x0 = __ldg(&pred[vi.x]);
        float x1 = __ldg(&pred[vi.y]);
        float x2 = __ldg(&pred[vi.z]);
        float x3 = __ldg(&pred[vi.w]);

        red_add_f32(&g_ax[ci.x], co.x * sigmoidf_fast(x0));
        red_add_f32(&g_ax[ci.y], co.y * sigmoidf_fast(x1));
        red_add_f32(&g_ax[ci.z], co.z * sigmoidf_fast(x2));
        red_add_f32(&g_ax[ci.w], co.w * sigmoidf_fast(x3));
    }
    // tail (nnz % 4)
    if (i == 0) {
        for (int j = nvec << 2; j < nnz; j++)
            red_add_f32(&g_ax[constr_idx[j]],
                        coeff[j] * sigmoidf_fast(__ldg(&pred[var_idx[j]])));
    }
}

// ---------------------------------------------------------------------------
// Kernel 2: violations + reduce + finalize + RESTORE (ax := 0, g_sum := 0).
// ---------------------------------------------------------------------------
__global__ void reduce_kernel(const float* __restrict__ rhs,
                              const int*   __restrict__ sense,
                              int n_constrs,
                              float* __restrict__ out,
                              int n_blocks)
{
    float local = 0.0f;
    int stride = gridDim.x * blockDim.x;
    int nc4 = n_constrs >> 2;
    const float4 zero4 = make_float4(0.f, 0.f, 0.f, 0.f);

    for (int i = blockIdx.x * blockDim.x + threadIdx.x; i < nc4; i += stride) {
        float4 ax = reinterpret_cast<const float4*>(g_ax)[i];
        float4 r  = reinterpret_cast<const float4*>(rhs)[i];
        int4   s  = reinterpret_cast<const int4*>(sense)[i];

        // restore the zero invariant for the next call
        reinterpret_cast<float4*>(g_ax)[i] = zero4;

        float d0 = ax.x - r.x, d1 = ax.y - r.y, d2 = ax.z - r.z, d3 = ax.w - r.w;
        float v0 = (s.x == 1) ? fmaxf(d0, 0.f) : (s.x == 2) ? fmaxf(-d0, 0.f) : (s.x == 3) ? fabsf(d0) : 0.f;
        float v1 = (s.y == 1) ? fmaxf(d1, 0.f) : (s.y == 2) ? fmaxf(-d1, 0.f) : (s.y == 3) ? fabsf(d1) : 0.f;
        float v2 = (s.z == 1) ? fmaxf(d2, 0.f) : (s.z == 2) ? fmaxf(-d2, 0.f) : (s.z == 3) ? fabsf(d2) : 0.f;
        float v3 = (s.w == 1) ? fmaxf(d3, 0.f) : (s.w == 2) ? fmaxf(-d3, 0.f) : (s.w == 3) ? fabsf(d3) : 0.f;
        local += (v0 + v1) + (v2 + v3);
    }
    // scalar tail (also restores zeros)
    if (blockIdx.x == 0 && threadIdx.x == 0) {
        for (int j = nc4 << 2; j < n_constrs; j++) {
            float d = g_ax[j] - rhs[j];
            g_ax[j] = 0.0f;
            int s = sense[j];
            local += (s == 1) ? fmaxf(d, 0.f) : (s == 2) ? fmaxf(-d, 0.f) : (s == 3) ? fabsf(d) : 0.f;
        }
    }

    // warp reduce
    #pragma unroll
    for (int off = 16; off > 0; off >>= 1)
        local += __shfl_xor_sync(0xFFFFFFFFu, local, off);

    __shared__ float warp_sums[32];
    int lane = threadIdx.x & 31;
    int wid  = threadIdx.x >> 5;
    if (lane == 0) warp_sums[wid] = local;
    __syncthreads();
    int nwarps = blockDim.x >> 5;

    __shared__ bool is_last;
    if (wid == 0) {
        float b = (lane < nwarps) ? warp_sums[lane] : 0.0f;
        #pragma unroll
        for (int off = 16; off > 0; off >>= 1)
            b += __shfl_xor_sync(0xFFFFFFFFu, b, off);
        if (lane == 0) {
            atomicAdd(&g_sum, (double)b);
            __threadfence();
            // wraps to 0 after the last block -> g_done invariant restored
            unsigned int ticket = atomicInc(&g_done, (unsigned int)(n_blocks - 1));
            is_last = (ticket == (unsigned int)(n_blocks - 1));
        }
    }
    __syncthreads();
    if (is_last && threadIdx.x == 0) {
        out[0] = (float)(g_sum / (double)n_constrs);
        g_sum = 0.0;   // restore for next call
    }
}

// ---------------------------------------------------------------------------
// Launch: two kernels only.
// ---------------------------------------------------------------------------
extern "C" void kernel_launch(void* const* d_in, const int* in_sizes, int n_in,
                              void* d_out, int out_size)
{
    const float* pred       = (const float*)d_in[0];
    const int*   constr_idx = (const int*)  d_in[1];
    const int*   var_idx    = (const int*)  d_in[2];
    const float* coeff      = (const float*)d_in[3];
    const float* rhs        = (const float*)d_in[4];
    const int*   sense      = (const int*)  d_in[5];

    int nnz       = in_sizes[1];
    int n_constrs = in_sizes[4];

    // 1) fused sigmoid + scatter — 4 nnz per thread, exact grid
    {
        int threads = 256;
        int nvec    = nnz >> 2;
        int blocks  = (nvec + threads - 1) / threads;
        if (blocks < 1) blocks = 1;
        scatter_kernel<<<blocks, threads>>>(pred, constr_idx, var_idx, coeff, nnz);
    }

    // 2) reduce + finalize + state restore
    {
        int threads = 256;
        int work    = n_constrs >> 2;
        int blocks  = (work + threads * 4 - 1) / (threads * 4);
        if (blocks < 1) blocks = 1;
        reduce_kernel<<<blocks, threads>>>(rhs, sense, n_constrs, (float*)d_out, blocks);
    }
}

// round 5
// speedup vs baseline: 1.0839x; 1.0483x over previous
#include <cuda_runtime.h>
#include <cuda_bf16.h>
#include <cstdint>

#define N_VARS_MAX    1000000
#define N_CONSTRS_MAX 500000

// Zero-initialized at module load; reduce_kernel restores zeros after each use,
// so every kernel_launch call sees ax == 0 (graph-replay safe, deterministic).
__device__ float        g_ax[N_CONSTRS_MAX];
__device__ double       g_sum;          // reset by last reduce block each call
__device__ unsigned int g_done;         // wraps back to 0 via atomicInc

// ---------------------------------------------------------------------------
// Kernel 1: fused sigmoid + scatter.
//   ax[cidx] += coeff * sigmoid(pred[vidx])
// 4 nnz per thread, plain loads, exact grid (best measured config).
// ---------------------------------------------------------------------------
__device__ __forceinline__ void red_add_f32(float* addr, float val)
{
    asm volatile("red.global.add.f32 [%0], %1;" :: "l"(addr), "f"(val) : "memory");
}

__device__ __forceinline__ float sigmoidf_fast(float x)
{
    return 1.0f / (1.0f + __expf(-x));
}

__global__ void scatter_kernel(const float* __restrict__ pred,
                               const int*   __restrict__ constr_idx,
                               const int*   __restrict__ var_idx,
                               const float* __restrict__ coeff,
                               int nnz)
{
    int nvec = nnz >> 2;
    int i = blockIdx.x * blockDim.x + threadIdx.x;
    if (i < nvec) {
        int4   ci = reinterpret_cast<const int4*>(constr_idx)[i];
        int4   vi = reinterpret_cast<const int4*>(var_idx)[i];
        float4 co = reinterpret_cast<const float4*>(coeff)[i];

        // 4 independent gathers first (MLP=4)
        float x0 = __ldg(&pred[vi.x]);
        float x1 = __ldg(&pred[vi.y]);
        float x2 = __ldg(&pred[vi.z]);
        float x3 = __ldg(&pred[vi.w]);

        red_add_f32(&g_ax[ci.x], co.x * sigmoidf_fast(x0));
        red_add_f32(&g_ax[ci.y], co.y * sigmoidf_fast(x1));
        red_add_f32(&g_ax[ci.z], co.z * sigmoidf_fast(x2));
        red_add_f32(&g_ax[ci.w], co.w * sigmoidf_fast(x3));
    }
    // tail (nnz % 4)
    if (i == 0) {
        for (int j = nvec << 2; j < nnz; j++)
            red_add_f32(&g_ax[constr_idx[j]],
                        coeff[j] * sigmoidf_fast(__ldg(&pred[var_idx[j]])));
    }
}

// ---------------------------------------------------------------------------
// Kernel 2: violations + reduce + finalize + RESTORE (ax := 0, g_sum := 0).
// Exact grid: one float4 per thread (no grid-stride loop) -> enough warps in
// flight to cover DRAM/L2 latency (R4 showed 123 blocks was latency-bound).
// ---------------------------------------------------------------------------
__global__ void reduce_kernel(const float* __restrict__ rhs,
                              const int*   __restrict__ sense,
                              int n_constrs,
                              float* __restrict__ out,
                              int n_blocks)
{
    float local = 0.0f;
    int nc4 = n_constrs >> 2;
    int i = blockIdx.x * blockDim.x + threadIdx.x;

    if (i < nc4) {
        // all three loads issued before the restore-store
        float4 ax = reinterpret_cast<const float4*>(g_ax)[i];
        float4 r  = reinterpret_cast<const float4*>(rhs)[i];
        int4   s  = reinterpret_cast<const int4*>(sense)[i];

        float d0 = ax.x - r.x, d1 = ax.y - r.y, d2 = ax.z - r.z, d3 = ax.w - r.w;
        float v0 = (s.x == 1) ? fmaxf(d0, 0.f) : (s.x == 2) ? fmaxf(-d0, 0.f) : (s.x == 3) ? fabsf(d0) : 0.f;
        float v1 = (s.y == 1) ? fmaxf(d1, 0.f) : (s.y == 2) ? fmaxf(-d1, 0.f) : (s.y == 3) ? fabsf(d1) : 0.f;
        float v2 = (s.z == 1) ? fmaxf(d2, 0.f) : (s.z == 2) ? fmaxf(-d2, 0.f) : (s.z == 3) ? fabsf(d2) : 0.f;
        float v3 = (s.w == 1) ? fmaxf(d3, 0.f) : (s.w == 2) ? fmaxf(-d3, 0.f) : (s.w == 3) ? fabsf(d3) : 0.f;
        local = (v0 + v1) + (v2 + v3);

        // restore the zero invariant for the next call
        reinterpret_cast<float4*>(g_ax)[i] = make_float4(0.f, 0.f, 0.f, 0.f);
    }
    // scalar tail (n_constrs % 4), also restores zeros
    if (blockIdx.x == 0 && threadIdx.x == 0) {
        for (int j = nc4 << 2; j < n_constrs; j++) {
            float d = g_ax[j] - rhs[j];
            g_ax[j] = 0.0f;
            int s = sense[j];
            local += (s == 1) ? fmaxf(d, 0.f) : (s == 2) ? fmaxf(-d, 0.f) : (s == 3) ? fabsf(d) : 0.f;
        }
    }

    // warp reduce
    #pragma unroll
    for (int off = 16; off > 0; off >>= 1)
        local += __shfl_xor_sync(0xFFFFFFFFu, local, off);

    __shared__ float warp_sums[32];
    int lane = threadIdx.x & 31;
    int wid  = threadIdx.x >> 5;
    if (lane == 0) warp_sums[wid] = local;
    __syncthreads();
    int nwarps = blockDim.x >> 5;

    __shared__ bool is_last;
    if (wid == 0) {
        float b = (lane < nwarps) ? warp_sums[lane] : 0.0f;
        #pragma unroll
        for (int off = 16; off > 0; off >>= 1)
            b += __shfl_xor_sync(0xFFFFFFFFu, b, off);
        if (lane == 0) {
            atomicAdd(&g_sum, (double)b);
            __threadfence();
            // wraps to 0 after the last block -> g_done invariant restored
            unsigned int ticket = atomicInc(&g_done, (unsigned int)(n_blocks - 1));
            is_last = (ticket == (unsigned int)(n_blocks - 1));
        }
    }
    __syncthreads();
    if (is_last && threadIdx.x == 0) {
        out[0] = (float)(g_sum / (double)n_constrs);
        g_sum = 0.0;   // restore for next call
    }
}

// ---------------------------------------------------------------------------
// Launch: two kernels only.
// ---------------------------------------------------------------------------
extern "C" void kernel_launch(void* const* d_in, const int* in_sizes, int n_in,
                              void* d_out, int out_size)
{
    const float* pred       = (const float*)d_in[0];
    const int*   constr_idx = (const int*)  d_in[1];
    const int*   var_idx    = (const int*)  d_in[2];
    const float* coeff      = (const float*)d_in[3];
    const float* rhs        = (const float*)d_in[4];
    const int*   sense      = (const int*)  d_in[5];

    int nnz       = in_sizes[1];
    int n_constrs = in_sizes[4];

    // 1) fused sigmoid + scatter — 4 nnz per thread, exact grid
    {
        int threads = 256;
        int nvec    = nnz >> 2;
        int blocks  = (nvec + threads - 1) / threads;
        if (blocks < 1) blocks = 1;
        scatter_kernel<<<blocks, threads>>>(pred, constr_idx, var_idx, coeff, nnz);
    }

    // 2) reduce + finalize + state restore — one float4 per thread
    {
        int threads = 256;
        int work    = n_constrs >> 2;
        int blocks  = (work + threads - 1) / threads;
        if (blocks < 1) blocks = 1;
        reduce_kernel<<<blocks, threads>>>(rhs, sense, n_constrs, (float*)d_out, blocks);
    }
}